// round 6
// baseline (speedup 1.0000x reference)
#include <cuda_runtime.h>

#define B 32
#define NN 128
#define DW 135
#define OBS 7
#define F 64
#define OD 4

// -------- device scratch (no allocations allowed) --------
__device__ __align__(16) float g_norm[B][NN];
__device__ float g_bmax[B];
__device__ __align__(16) float g_c[B][NN][F];      // c[j][f], f<63 valid, [63]=0
__device__ __align__(16) float g_cur[2][B][NN][F];
__device__ __align__(16) float g_edge[B][NN][F];
__device__ __align__(16) float g_P[B][OD];
__device__ __align__(16) float g_A[B][NN][OD];
__device__ __align__(16) float g_C[B][NN][OD];

// ---------------- K1: norm + per-batch max + c[j] + init_emb ----------------
__global__ void __launch_bounds__(128) k1_init(const float* __restrict__ obs,
                                               const float* __restrict__ Wi,
                                               const float* __restrict__ Wee) {
    int b = blockIdx.x;
    int j = threadIdx.x;              // node index 0..127
    __shared__ float sWi[F * OBS];
    __shared__ float sWee[63 * OBS];
    __shared__ int s_cnt[128];
    for (int t = j; t < F * OBS; t += 128) sWi[t] = Wi[t];
    for (int t = j; t < 63 * OBS; t += 128) {
        int f = t / OBS, k = t % OBS;
        sWee[t] = Wee[f * 8 + 1 + k];
    }
    __syncthreads();

    const float* ob = obs + (size_t)b * NN * DW;

    int cnt = 0;
#pragma unroll 8
    for (int i = 0; i < NN; i++)
        cnt += (ob[i * DW + OBS + j] != 0.0f);
    if (cnt == 0) cnt = 1;
    g_norm[b][j] = (float)cnt;
    s_cnt[j] = cnt;

    float nf[OBS];
#pragma unroll
    for (int k = 0; k < OBS; k++) nf[k] = ob[j * DW + k];

#pragma unroll 4
    for (int f = 0; f < F; f++) {
        float a = 0.f;
#pragma unroll
        for (int k = 0; k < OBS; k++) a = fmaf(nf[k], sWi[f * OBS + k], a);
        g_cur[0][b][j][f] = fmaxf(a, 0.f);
    }
#pragma unroll 4
    for (int f = 0; f < 63; f++) {
        float a = 0.f;
#pragma unroll
        for (int k = 0; k < OBS; k++) a = fmaf(nf[k], sWee[f * OBS + k], a);
        g_c[b][j][f] = a;
    }
    g_c[b][j][63] = 0.f;

    __syncthreads();
#pragma unroll
    for (int s = 64; s > 0; s >>= 1) {
        if (j < s) s_cnt[j] = max(s_cnt[j], s_cnt[j + s]);
        __syncthreads();
    }
    if (j == 0) g_bmax[b] = (float)s_cnt[0];
}

// ---------------- K2: edge aggregation + edge_emb ----------------
#define K2_NPB 8
#define K2_SMEM_FLOATS (8192 + 1024 + 4160 + 512 + 64 + 33)
#define K2_SMEM_BYTES  (K2_SMEM_FLOATS * 4)
__global__ void __launch_bounds__(512) k2_edge(const float* __restrict__ obs,
                                               const float* __restrict__ Wee,
                                               const float* __restrict__ Wef) {
    extern __shared__ float sm2[];
    float* s_c   = sm2;
    float* s_adj = s_c + 8192;
    float* s_WT  = s_adj + 1024;    // [k][f] stride 65
    float* s_x   = s_WT + 4160;
    float* s_w0  = s_x + 512;
    float* s_red = s_w0 + 64;

    int b = blockIdx.y;
    int itile = blockIdx.x;
    int tid = threadIdx.x;
    int f = tid & 63, q = tid >> 6;
    int i = itile * K2_NPB + q;

    const float* ob = obs + (size_t)b * NN * DW;

    {
        const float4* src = (const float4*)&g_c[b][0][0];
        float4* dst = (float4*)s_c;
        for (int t = tid; t < 2048; t += 512) dst[t] = src[t];
    }
    for (int t = tid; t < K2_NPB * NN; t += 512) {
        int il = t >> 7, j = t & 127;
        s_adj[t] = ob[(itile * K2_NPB + il) * DW + OBS + j];
    }
    for (int t = tid; t < F * F; t += 512) {
        int ff = t >> 6, k = t & 63;
        s_WT[k * 65 + ff] = Wef[t];
    }
    if (tid < F) s_w0[tid] = (tid < 63) ? Wee[tid * 8] : 0.f;
    if (tid < 32) s_red[tid] = g_bmax[tid];
    __syncthreads();
    if (tid == 0) {
        float m = s_red[0];
        for (int t = 1; t < 32; t++) m = fmaxf(m, s_red[t]);
        s_red[32] = m;
    }
    __syncthreads();

    float w0 = s_w0[f];
    float s = 0.f;
    const float* arow = &s_adj[q * 128];
#pragma unroll 8
    for (int j = 0; j < NN; j++) {
        float a = arow[j];
        float e = fmaxf(fmaf(a, w0, s_c[j * 64 + f]), 0.f);
        s += (a != 0.f) ? e : 0.f;
    }
    float nrm = g_norm[b][i];
    float mx = s_red[32];
    s_x[q * 64 + f] = (f < 63) ? (s / nrm) : (nrm / mx);
    __syncthreads();

    float acc = 0.f;
#pragma unroll 8
    for (int k = 0; k < F; k++) acc = fmaf(s_x[q * 64 + k], s_WT[k * 65 + f], acc);
    g_edge[b][i][f] = fmaxf(acc, 0.f);
}

// ---------------- K3: one message-passing layer ----------------
// 32 nodes/block, 512 threads: thread = (node il = tid>>4) x (fgroup fg = tid&15, 4 f).
// Both weight matrices resident in smem; padded strides to avoid bank conflicts.
#define K3_NPB 32
#define WTS 68      // weight row stride (floats)
#define PST 68      // per-node scratch stride (agg/edge/msg)
#define AST 132     // adj row stride
// floats: Wm 8704 | Wu 8704 | cur 8192 | adj 32*132=4224 | edge/agg/msg 3*32*68=6528 | inv 32
#define K3_SMEM_FLOATS (8704 * 2 + 8192 + 4224 + 6528 + 32)
#define K3_SMEM_BYTES  (K3_SMEM_FLOATS * 4)

__global__ void __launch_bounds__(512, 1) k3_layer(const float* __restrict__ obs,
                                                   const float* __restrict__ Wm,
                                                   const float* __restrict__ Wu,
                                                   int src, int dst) {
    extern __shared__ float sm[];
    float* s_Wm   = sm;                      // [k][f] stride WTS
    float* s_Wu   = s_Wm + 128 * WTS;
    float* s_cur  = s_Wu + 128 * WTS;        // [128][64]
    float* s_adj  = s_cur + 128 * 64;        // [32][AST]
    float* s_edge = s_adj + K3_NPB * AST;    // [32][PST]
    float* s_agg  = s_edge + K3_NPB * PST;
    float* s_msg  = s_agg + K3_NPB * PST;
    float* s_inv  = s_msg + K3_NPB * PST;

    int b = blockIdx.y, tile = blockIdx.x;
    int tid = threadIdx.x;
    int fg = tid & 15;          // feature quad
    int il = tid >> 4;          // local node 0..31
    int i0 = tile * K3_NPB;
    const float* ob = obs + (size_t)b * NN * DW;

    // ---- staging ----
    for (int t = tid; t < F * 2 * F; t += 512) {
        int ff = t >> 7, k = t & 127;
        s_Wm[k * WTS + ff] = Wm[t];
        s_Wu[k * WTS + ff] = Wu[t];
    }
    {
        const float4* src4 = (const float4*)&g_cur[src][b][0][0];
        float4* dst4 = (float4*)s_cur;
        for (int t = tid; t < 2048; t += 512) dst4[t] = src4[t];
        const float4* es = (const float4*)&g_edge[b][i0][0];
        for (int t = tid; t < 512; t += 512) {
            int r = t >> 4, q = t & 15;
            *(float4*)&s_edge[r * PST + q * 4] = es[t];
        }
    }
    for (int t = tid; t < K3_NPB * 128; t += 512) {
        int r = t >> 7, j = t & 127;
        s_adj[r * AST + j] = ob[(i0 + r) * DW + OBS + j];
    }
    if (tid < K3_NPB) s_inv[tid] = 1.0f / g_norm[b][i0 + tid];
    __syncthreads();

    // ---- agg = adj @ cur / norm ----
    {
        float4 a = make_float4(0.f, 0.f, 0.f, 0.f);
        const float* ar = &s_adj[il * AST];
        const float* cb = &s_cur[fg * 4];
#pragma unroll 8
        for (int j4 = 0; j4 < 32; j4++) {
            float4 av = *(const float4*)&ar[j4 * 4];
            float4 c0 = *(const float4*)&cb[(j4 * 4 + 0) * 64];
            float4 c1 = *(const float4*)&cb[(j4 * 4 + 1) * 64];
            float4 c2 = *(const float4*)&cb[(j4 * 4 + 2) * 64];
            float4 c3 = *(const float4*)&cb[(j4 * 4 + 3) * 64];
            a.x = fmaf(av.x, c0.x, fmaf(av.y, c1.x, fmaf(av.z, c2.x, fmaf(av.w, c3.x, a.x))));
            a.y = fmaf(av.x, c0.y, fmaf(av.y, c1.y, fmaf(av.z, c2.y, fmaf(av.w, c3.y, a.y))));
            a.z = fmaf(av.x, c0.z, fmaf(av.y, c1.z, fmaf(av.z, c2.z, fmaf(av.w, c3.z, a.z))));
            a.w = fmaf(av.x, c0.w, fmaf(av.y, c1.w, fmaf(av.z, c2.w, fmaf(av.w, c3.w, a.w))));
        }
        float iv = s_inv[il];
        a.x *= iv; a.y *= iv; a.z *= iv; a.w *= iv;
        *(float4*)&s_agg[il * PST + fg * 4] = a;
    }
    __syncthreads();

    // ---- msg = relu([agg, edge] @ Wm^T) ----
    {
        float4 m = make_float4(0.f, 0.f, 0.f, 0.f);
        const float* gr = &s_agg[il * PST];
        const float* er = &s_edge[il * PST];
#pragma unroll 8
        for (int k = 0; k < F; k++) {
            float4 w1 = *(const float4*)&s_Wm[k * WTS + fg * 4];
            float4 w2 = *(const float4*)&s_Wm[(F + k) * WTS + fg * 4];
            float g = gr[k], e = er[k];
            m.x = fmaf(g, w1.x, fmaf(e, w2.x, m.x));
            m.y = fmaf(g, w1.y, fmaf(e, w2.y, m.y));
            m.z = fmaf(g, w1.z, fmaf(e, w2.z, m.z));
            m.w = fmaf(g, w1.w, fmaf(e, w2.w, m.w));
        }
        m.x = fmaxf(m.x, 0.f); m.y = fmaxf(m.y, 0.f);
        m.z = fmaxf(m.z, 0.f); m.w = fmaxf(m.w, 0.f);
        *(float4*)&s_msg[il * PST + fg * 4] = m;
    }
    __syncthreads();

    // ---- cur' = relu([cur, msg] @ Wu^T) ----
    {
        float4 u = make_float4(0.f, 0.f, 0.f, 0.f);
        const float* cr = &s_cur[(i0 + il) * 64];
        const float* mr = &s_msg[il * PST];
#pragma unroll 8
        for (int k = 0; k < F; k++) {
            float4 w1 = *(const float4*)&s_Wu[k * WTS + fg * 4];
            float4 w2 = *(const float4*)&s_Wu[(F + k) * WTS + fg * 4];
            float cv = cr[k], mv = mr[k];
            u.x = fmaf(cv, w1.x, fmaf(mv, w2.x, u.x));
            u.y = fmaf(cv, w1.y, fmaf(mv, w2.y, u.y));
            u.z = fmaf(cv, w1.z, fmaf(mv, w2.z, u.z));
            u.w = fmaf(cv, w1.w, fmaf(mv, w2.w, u.w));
        }
        u.x = fmaxf(u.x, 0.f); u.y = fmaxf(u.y, 0.f);
        u.z = fmaxf(u.z, 0.f); u.w = fmaxf(u.w, 0.f);
        *(float4*)&g_cur[dst][b][i0 + il][fg * 4] = u;
    }
}

// ---------------- K4: pool + readout precompute ----------------
__global__ void __launch_bounds__(128) k4_pool(const float* __restrict__ Wp,
                                               const float* __restrict__ Wr,
                                               const float* __restrict__ br,
                                               int src) {
    int b = blockIdx.x;
    int tid = threadIdx.x;
    __shared__ float s_part[128];
    __shared__ float s_mean[F];
    __shared__ float s_rp[F];
    __shared__ float s_Wr[OD * 3 * F];   // 768

    for (int t = tid; t < OD * 3 * F; t += 128) s_Wr[t] = Wr[t];

    {
        int f = tid & 63, h = tid >> 6;
        float acc = 0.f;
        for (int i = h; i < NN; i += 2) acc += g_cur[src][b][i][f];
        s_part[tid] = acc;
    }
    __syncthreads();
    if (tid < F) s_mean[tid] = (s_part[tid] + s_part[tid + 64]) * (1.0f / NN);
    __syncthreads();
    if (tid < F) {
        float hp = 0.f;
#pragma unroll 8
        for (int k = 0; k < F; k++) hp = fmaf(s_mean[k], Wp[tid * 64 + k], hp);
        s_rp[tid] = fmaxf(hp, 0.f);
    }
    __syncthreads();
    if (tid < OD) {
        float p = br[tid];
#pragma unroll 8
        for (int f = 0; f < F; f++) p = fmaf(s_rp[f], s_Wr[tid * 192 + f], p);
        g_P[b][tid] = p;
    }
    int i = tid;
    float a[OD] = {0.f, 0.f, 0.f, 0.f};
    float c[OD] = {0.f, 0.f, 0.f, 0.f};
#pragma unroll 4
    for (int k = 0; k < F; k++) {
        float r = fmaxf(g_cur[src][b][i][k], 0.f);
#pragma unroll
        for (int o = 0; o < OD; o++) {
            a[o] = fmaf(r, s_Wr[o * 192 + 64 + k], a[o]);
            c[o] = fmaf(r, s_Wr[o * 192 + 128 + k], c[o]);
        }
    }
#pragma unroll
    for (int o = 0; o < OD; o++) {
        g_A[b][i][o] = a[o];
        g_C[b][i][o] = c[o];
    }
}

// ---------------- K5: output writer ----------------
__global__ void __launch_bounds__(512) k5_out(float* __restrict__ out) {
    int b = blockIdx.y;
    int tid = threadIdx.x;
    int j = tid & 127, iq = tid >> 7;
    int i = blockIdx.x * 4 + iq;
    float4 P = *(const float4*)&g_P[b][0];
    float4 A = *(const float4*)&g_A[b][i][0];
    float4 C = *(const float4*)&g_C[b][j][0];
    float4 r;
    r.x = P.x + A.x + C.x;
    r.y = P.y + A.y + C.y;
    r.z = P.z + A.z + C.z;
    r.w = P.w + A.w + C.w;
    ((float4*)out)[((size_t)b * NN + i) * NN + j] = r;
}

// ---------------- launch ----------------
extern "C" void kernel_launch(void* const* d_in, const int* in_sizes, int n_in,
                              void* d_out, int out_size) {
    const float* obs = (const float*)d_in[0];
    const float* Wi  = (const float*)d_in[1];
    const float* Wee = (const float*)d_in[2];
    const float* Wef = (const float*)d_in[3];
    const float* Wm  = (const float*)d_in[4];
    const float* Wu  = (const float*)d_in[5];
    const float* Wp  = (const float*)d_in[6];
    const float* Wr  = (const float*)d_in[7];
    const float* br  = (const float*)d_in[8];

    static int attr_done = 0;
    if (!attr_done) {
        cudaFuncSetAttribute(k3_layer, cudaFuncAttributeMaxDynamicSharedMemorySize, K3_SMEM_BYTES);
        cudaFuncSetAttribute(k2_edge, cudaFuncAttributeMaxDynamicSharedMemorySize, K2_SMEM_BYTES);
        attr_done = 1;
    }

    k1_init<<<B, 128>>>(obs, Wi, Wee);
    k2_edge<<<dim3(NN / K2_NPB, B), 512, K2_SMEM_BYTES>>>(obs, Wee, Wef);

    const int LW = F * 2 * F;  // 8192 floats per layer
    k3_layer<<<dim3(NN / K3_NPB, B), 512, K3_SMEM_BYTES>>>(obs, Wm + 0 * LW, Wu + 0 * LW, 0, 1);
    k3_layer<<<dim3(NN / K3_NPB, B), 512, K3_SMEM_BYTES>>>(obs, Wm + 1 * LW, Wu + 1 * LW, 1, 0);
    k3_layer<<<dim3(NN / K3_NPB, B), 512, K3_SMEM_BYTES>>>(obs, Wm + 2 * LW, Wu + 2 * LW, 0, 1);

    k4_pool<<<B, 128>>>(Wp, Wr, br, 1);
    k5_out<<<dim3(NN / 4, B), 512>>>((float*)d_out);
}

// round 10
// speedup vs baseline: 1.0622x; 1.0622x over previous
#include <cuda_runtime.h>

#define B 32
#define NN 128
#define DW 135
#define OBS 7
#define F 64
#define OD 4

// -------- device scratch (no allocations allowed) --------
__device__ __align__(16) float g_norm[B][NN];
__device__ float g_bmax[B];
__device__ __align__(16) float g_c[B][NN][F];      // c[j][f], f<63 valid, [63]=0
__device__ __align__(16) float g_cur[2][B][NN][F];
__device__ __align__(16) float g_edge[B][NN][F];
__device__ __align__(16) float g_P[B][OD];
__device__ __align__(16) float g_A[B][NN][OD];
__device__ __align__(16) float g_C[B][NN][OD];

// ---------------- K1: norm + per-batch max + c[j] + init_emb ----------------
__global__ void __launch_bounds__(128) k1_init(const float* __restrict__ obs,
                                               const float* __restrict__ Wi,
                                               const float* __restrict__ Wee) {
    int b = blockIdx.x;
    int j = threadIdx.x;              // node index 0..127
    __shared__ float sWi[F * OBS];
    __shared__ float sWee[63 * OBS];
    __shared__ int s_cnt[128];
    for (int t = j; t < F * OBS; t += 128) sWi[t] = Wi[t];
    for (int t = j; t < 63 * OBS; t += 128) {
        int f = t / OBS, k = t % OBS;
        sWee[t] = Wee[f * 8 + 1 + k];
    }
    __syncthreads();

    const float* ob = obs + (size_t)b * NN * DW;

    int cnt = 0;
#pragma unroll 8
    for (int i = 0; i < NN; i++)
        cnt += (ob[i * DW + OBS + j] != 0.0f);
    if (cnt == 0) cnt = 1;
    g_norm[b][j] = (float)cnt;
    s_cnt[j] = cnt;

    float nf[OBS];
#pragma unroll
    for (int k = 0; k < OBS; k++) nf[k] = ob[j * DW + k];

#pragma unroll 4
    for (int f = 0; f < F; f++) {
        float a = 0.f;
#pragma unroll
        for (int k = 0; k < OBS; k++) a = fmaf(nf[k], sWi[f * OBS + k], a);
        g_cur[0][b][j][f] = fmaxf(a, 0.f);
    }
#pragma unroll 4
    for (int f = 0; f < 63; f++) {
        float a = 0.f;
#pragma unroll
        for (int k = 0; k < OBS; k++) a = fmaf(nf[k], sWee[f * OBS + k], a);
        g_c[b][j][f] = a;
    }
    g_c[b][j][63] = 0.f;

    __syncthreads();
#pragma unroll
    for (int s = 64; s > 0; s >>= 1) {
        if (j < s) s_cnt[j] = max(s_cnt[j], s_cnt[j + s]);
        __syncthreads();
    }
    if (j == 0) g_bmax[b] = (float)s_cnt[0];
}

// ---------------- K2: edge aggregation + edge_emb ----------------
#define K2_NPB 8
#define K2_SMEM_FLOATS (8192 + 1024 + 4160 + 512 + 64 + 33)
#define K2_SMEM_BYTES  (K2_SMEM_FLOATS * 4)
__global__ void __launch_bounds__(512) k2_edge(const float* __restrict__ obs,
                                               const float* __restrict__ Wee,
                                               const float* __restrict__ Wef) {
    extern __shared__ float sm2[];
    float* s_c   = sm2;
    float* s_adj = s_c + 8192;
    float* s_WT  = s_adj + 1024;    // [k][f] stride 65
    float* s_x   = s_WT + 4160;
    float* s_w0  = s_x + 512;
    float* s_red = s_w0 + 64;

    int b = blockIdx.y;
    int itile = blockIdx.x;
    int tid = threadIdx.x;
    int f = tid & 63, q = tid >> 6;
    int i = itile * K2_NPB + q;

    const float* ob = obs + (size_t)b * NN * DW;

    {
        const float4* src = (const float4*)&g_c[b][0][0];
        float4* dst = (float4*)s_c;
        for (int t = tid; t < 2048; t += 512) dst[t] = src[t];
    }
    for (int t = tid; t < K2_NPB * NN; t += 512) {
        int il = t >> 7, j = t & 127;
        s_adj[t] = ob[(itile * K2_NPB + il) * DW + OBS + j];
    }
    for (int t = tid; t < F * F; t += 512) {
        int ff = t >> 6, k = t & 63;
        s_WT[k * 65 + ff] = Wef[t];
    }
    if (tid < F) s_w0[tid] = (tid < 63) ? Wee[tid * 8] : 0.f;
    if (tid < 32) s_red[tid] = g_bmax[tid];
    __syncthreads();
    if (tid == 0) {
        float m = s_red[0];
        for (int t = 1; t < 32; t++) m = fmaxf(m, s_red[t]);
        s_red[32] = m;
    }
    __syncthreads();

    float w0 = s_w0[f];
    float s = 0.f;
    const float* arow = &s_adj[q * 128];
#pragma unroll 8
    for (int j = 0; j < NN; j++) {
        float a = arow[j];
        float e = fmaxf(fmaf(a, w0, s_c[j * 64 + f]), 0.f);
        s += (a != 0.f) ? e : 0.f;
    }
    float nrm = g_norm[b][i];
    float mx = s_red[32];
    s_x[q * 64 + f] = (f < 63) ? (s / nrm) : (nrm / mx);
    __syncthreads();

    float acc = 0.f;
#pragma unroll 8
    for (int k = 0; k < F; k++) acc = fmaf(s_x[q * 64 + k], s_WT[k * 65 + f], acc);
    g_edge[b][i][f] = fmaxf(acc, 0.f);
}

// ---------------- K3: one message-passing layer (outer-product layout) ----------------
// 256 threads = 8 warps. lane = node (32 nodes/block), warp = 8 output feats.
// Weights read as BROADCAST float4 (1 crossbar phase); activations via transposed
// stride-33 buffers (conflict-free scalar access).
#define K3_NPB 32
#define WST 68     // transposed weight row stride
#define TST 33     // transposed activation row stride
#define AST 129    // adj row stride

// floats: Wm 8704 | Wu 8704 | cur 8192 | adj 32*129=4128 | in1 128*33=4224 | in2 4224 | inv 32
#define K3_SMEM_FLOATS (8704 * 2 + 8192 + 4128 + 4224 * 2 + 32)
#define K3_SMEM_BYTES  (K3_SMEM_FLOATS * 4)

__global__ void __launch_bounds__(256, 1) k3_layer(const float* __restrict__ obs,
                                                   const float* __restrict__ Wm,
                                                   const float* __restrict__ Wu,
                                                   int src, int dst) {
    extern __shared__ float sm[];
    float* s_Wm  = sm;                      // [k][f] stride WST
    float* s_Wu  = s_Wm + 128 * WST;
    float* s_cur = s_Wu + 128 * WST;        // dense [128][64]
    float* s_adj = s_cur + 128 * 64;        // [32][AST]
    float* s_in1 = s_adj + K3_NPB * AST;    // [128][TST]: rows 0..63 aggT, 64..127 edgeT
    float* s_in2 = s_in1 + 128 * TST;       // [128][TST]: rows 0..63 curT, 64..127 msgT
    float* s_inv = s_in2 + 128 * TST;

    int b = blockIdx.y, tile = blockIdx.x;
    int tid = threadIdx.x;
    int il = tid & 31;          // node lane
    int w  = tid >> 5;          // warp -> out feats [8w, 8w+8)
    int i0 = tile * K3_NPB;
    const float* ob = obs + (size_t)b * NN * DW;

    // ---- staging ----
    for (int t = tid; t < F * 2 * F; t += 256) {   // transpose both weights
        int ff = t >> 7, k = t & 127;
        s_Wm[k * WST + ff] = Wm[t];
        s_Wu[k * WST + ff] = Wu[t];
    }
    {
        const float4* src4 = (const float4*)&g_cur[src][b][0][0];
        float4* dst4 = (float4*)s_cur;
        for (int t = tid; t < 2048; t += 256) dst4[t] = src4[t];
    }
    // curT + edgeT (rows of s_in2 / s_in1), coalesced global reads
    for (int t = tid; t < K3_NPB * F; t += 256) {
        int node = t >> 6, f = t & 63;
        s_in2[f * TST + node] = g_cur[src][b][i0 + node][f];
        s_in1[(64 + f) * TST + node] = g_edge[b][i0 + node][f];
    }
    for (int t = tid; t < K3_NPB * 128; t += 256) {
        int r = t >> 7, j = t & 127;
        s_adj[r * AST + j] = ob[(i0 + r) * DW + OBS + j];
    }
    if (tid < K3_NPB) s_inv[tid] = 1.0f / g_norm[b][i0 + tid];
    __syncthreads();

    // ---- agg = adj @ cur / norm : acc[q] for node il, feats 8w+q ----
    {
        float a0 = 0.f, a1 = 0.f, a2 = 0.f, a3 = 0.f;
        float a4 = 0.f, a5 = 0.f, a6 = 0.f, a7 = 0.f;
        const float* ar = &s_adj[il * AST];
        const float* cb = &s_cur[w * 8];
#pragma unroll 8
        for (int j = 0; j < NN; j++) {
            float av = ar[j];
            float4 c0 = *(const float4*)&cb[j * 64];
            float4 c1 = *(const float4*)&cb[j * 64 + 4];
            a0 = fmaf(av, c0.x, a0); a1 = fmaf(av, c0.y, a1);
            a2 = fmaf(av, c0.z, a2); a3 = fmaf(av, c0.w, a3);
            a4 = fmaf(av, c1.x, a4); a5 = fmaf(av, c1.y, a5);
            a6 = fmaf(av, c1.z, a6); a7 = fmaf(av, c1.w, a7);
        }
        float iv = s_inv[il];
        float* o = &s_in1[(w * 8) * TST + il];
        o[0 * TST] = a0 * iv; o[1 * TST] = a1 * iv;
        o[2 * TST] = a2 * iv; o[3 * TST] = a3 * iv;
        o[4 * TST] = a4 * iv; o[5 * TST] = a5 * iv;
        o[6 * TST] = a6 * iv; o[7 * TST] = a7 * iv;
    }
    __syncthreads();

    // ---- msg = relu([agg, edge] @ Wm^T) ----
    {
        float m0 = 0.f, m1 = 0.f, m2 = 0.f, m3 = 0.f;
        float m4 = 0.f, m5 = 0.f, m6 = 0.f, m7 = 0.f;
        const float* ab = &s_in1[il];
        const float* wb = &s_Wm[w * 8];
#pragma unroll 8
        for (int k = 0; k < 2 * F; k++) {
            float av = ab[k * TST];
            float4 w0 = *(const float4*)&wb[k * WST];
            float4 w1 = *(const float4*)&wb[k * WST + 4];
            m0 = fmaf(av, w0.x, m0); m1 = fmaf(av, w0.y, m1);
            m2 = fmaf(av, w0.z, m2); m3 = fmaf(av, w0.w, m3);
            m4 = fmaf(av, w1.x, m4); m5 = fmaf(av, w1.y, m5);
            m6 = fmaf(av, w1.z, m6); m7 = fmaf(av, w1.w, m7);
        }
        float* o = &s_in2[(64 + w * 8) * TST + il];
        o[0 * TST] = fmaxf(m0, 0.f); o[1 * TST] = fmaxf(m1, 0.f);
        o[2 * TST] = fmaxf(m2, 0.f); o[3 * TST] = fmaxf(m3, 0.f);
        o[4 * TST] = fmaxf(m4, 0.f); o[5 * TST] = fmaxf(m5, 0.f);
        o[6 * TST] = fmaxf(m6, 0.f); o[7 * TST] = fmaxf(m7, 0.f);
    }
    __syncthreads();

    // ---- cur' = relu([cur, msg] @ Wu^T) ----
    {
        float u0 = 0.f, u1 = 0.f, u2 = 0.f, u3 = 0.f;
        float u4 = 0.f, u5 = 0.f, u6 = 0.f, u7 = 0.f;
        const float* ab = &s_in2[il];
        const float* wb = &s_Wu[w * 8];
#pragma unroll 8
        for (int k = 0; k < 2 * F; k++) {
            float av = ab[k * TST];
            float4 w0 = *(const float4*)&wb[k * WST];
            float4 w1 = *(const float4*)&wb[k * WST + 4];
            u0 = fmaf(av, w0.x, u0); u1 = fmaf(av, w0.y, u1);
            u2 = fmaf(av, w0.z, u2); u3 = fmaf(av, w0.w, u3);
            u4 = fmaf(av, w1.x, u4); u5 = fmaf(av, w1.y, u5);
            u6 = fmaf(av, w1.z, u6); u7 = fmaf(av, w1.w, u7);
        }
        float4 r0 = make_float4(fmaxf(u0, 0.f), fmaxf(u1, 0.f), fmaxf(u2, 0.f), fmaxf(u3, 0.f));
        float4 r1 = make_float4(fmaxf(u4, 0.f), fmaxf(u5, 0.f), fmaxf(u6, 0.f), fmaxf(u7, 0.f));
        *(float4*)&g_cur[dst][b][i0 + il][w * 8]     = r0;
        *(float4*)&g_cur[dst][b][i0 + il][w * 8 + 4] = r1;
    }
}

// ---------------- K4: pool + readout precompute ----------------
__global__ void __launch_bounds__(128) k4_pool(const float* __restrict__ Wp,
                                               const float* __restrict__ Wr,
                                               const float* __restrict__ br,
                                               int src) {
    int b = blockIdx.x;
    int tid = threadIdx.x;
    __shared__ float s_part[128];
    __shared__ float s_mean[F];
    __shared__ float s_rp[F];
    __shared__ float s_Wr[OD * 3 * F];   // 768

    for (int t = tid; t < OD * 3 * F; t += 128) s_Wr[t] = Wr[t];

    {
        int f = tid & 63, h = tid >> 6;
        float acc = 0.f;
        for (int i = h; i < NN; i += 2) acc += g_cur[src][b][i][f];
        s_part[tid] = acc;
    }
    __syncthreads();
    if (tid < F) s_mean[tid] = (s_part[tid] + s_part[tid + 64]) * (1.0f / NN);
    __syncthreads();
    if (tid < F) {
        float hp = 0.f;
#pragma unroll 8
        for (int k = 0; k < F; k++) hp = fmaf(s_mean[k], Wp[tid * 64 + k], hp);
        s_rp[tid] = fmaxf(hp, 0.f);
    }
    __syncthreads();
    if (tid < OD) {
        float p = br[tid];
#pragma unroll 8
        for (int f = 0; f < F; f++) p = fmaf(s_rp[f], s_Wr[tid * 192 + f], p);
        g_P[b][tid] = p;
    }
    int i = tid;
    float a[OD] = {0.f, 0.f, 0.f, 0.f};
    float c[OD] = {0.f, 0.f, 0.f, 0.f};
#pragma unroll 4
    for (int k = 0; k < F; k++) {
        float r = fmaxf(g_cur[src][b][i][k], 0.f);
#pragma unroll
        for (int o = 0; o < OD; o++) {
            a[o] = fmaf(r, s_Wr[o * 192 + 64 + k], a[o]);
            c[o] = fmaf(r, s_Wr[o * 192 + 128 + k], c[o]);
        }
    }
#pragma unroll
    for (int o = 0; o < OD; o++) {
        g_A[b][i][o] = a[o];
        g_C[b][i][o] = c[o];
    }
}

// ---------------- K5: output writer ----------------
__global__ void __launch_bounds__(512) k5_out(float* __restrict__ out) {
    int b = blockIdx.y;
    int tid = threadIdx.x;
    int j = tid & 127, iq = tid >> 7;
    int i = blockIdx.x * 4 + iq;
    float4 P = *(const float4*)&g_P[b][0];
    float4 A = *(const float4*)&g_A[b][i][0];
    float4 C = *(const float4*)&g_C[b][j][0];
    float4 r;
    r.x = P.x + A.x + C.x;
    r.y = P.y + A.y + C.y;
    r.z = P.z + A.z + C.z;
    r.w = P.w + A.w + C.w;
    ((float4*)out)[((size_t)b * NN + i) * NN + j] = r;
}

// ---------------- launch ----------------
extern "C" void kernel_launch(void* const* d_in, const int* in_sizes, int n_in,
                              void* d_out, int out_size) {
    const float* obs = (const float*)d_in[0];
    const float* Wi  = (const float*)d_in[1];
    const float* Wee = (const float*)d_in[2];
    const float* Wef = (const float*)d_in[3];
    const float* Wm  = (const float*)d_in[4];
    const float* Wu  = (const float*)d_in[5];
    const float* Wp  = (const float*)d_in[6];
    const float* Wr  = (const float*)d_in[7];
    const float* br  = (const float*)d_in[8];

    static int attr_done = 0;
    if (!attr_done) {
        cudaFuncSetAttribute(k3_layer, cudaFuncAttributeMaxDynamicSharedMemorySize, K3_SMEM_BYTES);
        cudaFuncSetAttribute(k2_edge, cudaFuncAttributeMaxDynamicSharedMemorySize, K2_SMEM_BYTES);
        attr_done = 1;
    }

    k1_init<<<B, 128>>>(obs, Wi, Wee);
    k2_edge<<<dim3(NN / K2_NPB, B), 512, K2_SMEM_BYTES>>>(obs, Wee, Wef);

    const int LW = F * 2 * F;  // 8192 floats per layer
    k3_layer<<<dim3(NN / K3_NPB, B), 256, K3_SMEM_BYTES>>>(obs, Wm + 0 * LW, Wu + 0 * LW, 0, 1);
    k3_layer<<<dim3(NN / K3_NPB, B), 256, K3_SMEM_BYTES>>>(obs, Wm + 1 * LW, Wu + 1 * LW, 1, 0);
    k3_layer<<<dim3(NN / K3_NPB, B), 256, K3_SMEM_BYTES>>>(obs, Wm + 2 * LW, Wu + 2 * LW, 0, 1);

    k4_pool<<<B, 128>>>(Wp, Wr, br, 1);
    k5_out<<<dim3(NN / 4, B), 512>>>((float*)d_out);
}